// round 6
// baseline (speedup 1.0000x reference)
#include <cuda_runtime.h>
#include <math.h>

#define N 2048
#define IN_DIM 128
#define OUT_DIM 32
#define ROWS 8
#define NWARPS 8
#define TABSZ 1024
#define JSPLIT 4
#define JCHUNK (N / JSPLIT)          // 512 j's per block
#define NBATCH (JCHUNK / 32)         // 16 batches of 32 j's
#define NGROUPS (N / ROWS)           // 256 row-groups

#define PREP_BLKS (N / 4)                        // 512 (4 rows/block, split-K)
#define TAB_BLKS  ((TABSZ + 1 + 7) / 8)          // 129 (8 q's per block)

// Scratch (allocation-free rule: __device__ globals)
__device__ float g_z[N * OUT_DIM];
__device__ float g_src[N];
__device__ float g_dst[N];
__device__ float g_val[TABSZ + 1];
__device__ float g_maxdst = -1e30f;   // reset by last finisher (graph-safe)
__device__ float g_maxg   = -1e30f;
__device__ float g_pl[N * JSPLIT];               // partial softmax denominators
__device__ float g_pa[N * JSPLIT * OUT_DIM];     // partial att@z accumulators
__device__ unsigned g_cnt[NGROUPS];              // zero-init; reset by finisher
__device__ unsigned g_done = 0;                  // reset by last finisher

__device__ __forceinline__ float atomicMaxFloat(float* addr, float value) {
    return (value >= 0.f)
        ? __int_as_float(atomicMax((int*)addr, __float_as_int(value)))
        : __uint_as_float(atomicMin((unsigned*)addr, __float_as_uint(value)));
}

// ---------------------------------------------------------------------------
// Fused prologue. Blocks [0,512): z = feat@W (split-K: 2 warps per row,
// 64 dims each, W staged in smem), src, dst (+ dst max atomic).
// Blocks [512,641): e_time lookup table (+ table max atomic).
// ---------------------------------------------------------------------------
__global__ void __launch_bounds__(256)
prep_kernel(const float* __restrict__ feat,
            const float* __restrict__ a,
            const float* __restrict__ W,
            const int*   __restrict__ te,
            const float* __restrict__ bf) {
    const int warp = threadIdx.x >> 5;
    const int lane = threadIdx.x & 31;
    __shared__ float s_W[IN_DIM * OUT_DIM];      // 16 KB
    __shared__ float s_part[4][2][OUT_DIM];
    __shared__ float s_red[8];

    if (blockIdx.x < PREP_BLKS) {
        // Stage W in smem: 1024 float4, 4 per thread.
        const float4* wsrc = (const float4*)W;
        float4*       wdst = (float4*)s_W;
#pragma unroll
        for (int t = 0; t < 4; ++t)
            wdst[threadIdx.x + 256 * t] = wsrc[threadIdx.x + 256 * t];
        __syncthreads();

        const int r    = warp >> 1;              // 0..3  row within block
        const int half = warp & 1;               // 0..1  K-split
        const int i    = blockIdx.x * 4 + r;
        const float4* f4 = (const float4*)(feat + i * IN_DIM) + half * 16;
        const float*  Wm = s_W + half * 64 * OUT_DIM;
        float a0 = 0.f, a1 = 0.f, a2 = 0.f, a3 = 0.f;
#pragma unroll
        for (int d4 = 0; d4 < 16; ++d4) {
            float4 f = f4[d4];                   // uniform (broadcast)
            a0 = fmaf(f.x, Wm[(d4 * 4 + 0) * OUT_DIM + lane], a0);
            a1 = fmaf(f.y, Wm[(d4 * 4 + 1) * OUT_DIM + lane], a1);
            a2 = fmaf(f.z, Wm[(d4 * 4 + 2) * OUT_DIM + lane], a2);
            a3 = fmaf(f.w, Wm[(d4 * 4 + 3) * OUT_DIM + lane], a3);
        }
        s_part[r][half][lane] = (a0 + a1) + (a2 + a3);
        __syncthreads();

        if (warp < 4) {
            const int i2 = blockIdx.x * 4 + warp;
            float acc = s_part[warp][0][lane] + s_part[warp][1][lane];
            g_z[i2 * OUT_DIM + lane] = acc;
            float s = acc * a[lane];
            float t = acc * a[OUT_DIM + lane];
#pragma unroll
            for (int o = 16; o > 0; o >>= 1) {
                s += __shfl_xor_sync(0xffffffffu, s, o);
                t += __shfl_xor_sync(0xffffffffu, t, o);
            }
            if (lane == 0) { g_src[i2] = s; g_dst[i2] = t; s_red[warp] = t; }
        }
        __syncthreads();
        if (threadIdx.x == 0) {
            float md = fmaxf(fmaxf(s_red[0], s_red[1]),
                             fmaxf(s_red[2], s_red[3]));
            atomicMaxFloat(&g_maxdst, md);
        }
    } else {
        // Table: warp w computes q; 8 q's per block.
        const int q = (blockIdx.x - PREP_BLKS) * 8 + warp;
        float v = -1e30f;
        if (q <= TABSZ) {
            int ti = *te;
            float T = (ti > -1000000 && ti < 1000000) ? (float)ti
                                                      : __int_as_float(ti);
            float tsv = (float)q / (float)TABSZ;
            float dt  = T - tsv;
            float th  = dt * bf[lane];
            v = a[2 * lane] * sinf(th) + a[2 * lane + 1] * cosf(th);
#pragma unroll
            for (int o = 16; o > 0; o >>= 1)
                v += __shfl_xor_sync(0xffffffffu, v, o);
            if (lane == 0) g_val[q] = v;
        }
        if (lane == 0) s_red[warp] = v;
        __syncthreads();
        if (threadIdx.x == 0) {
            float mg = s_red[0];
#pragma unroll
            for (int w = 1; w < 8; ++w) mg = fmaxf(mg, s_red[w]);
            atomicMaxFloat(&g_maxg, mg);
        }
    }
}

// ---------------------------------------------------------------------------
// Fused attention + (threadfence-reduction) epilogue.
// grid = (NGROUPS, JSPLIT). Lane-parallel scores; fixed softmax shift
// (analytic upper bound -> exp in (0,1], branch-free); PV via smem-staged p
// tile + broadcast LDS.128. Last split-block per row-group finalizes:
// partial sums + residual + layernorm. Very last finisher resets globals.
// ---------------------------------------------------------------------------
__global__ void __launch_bounds__(256)
attn_kernel(const int*   __restrict__ adj,
            const float* __restrict__ ts,
            const float* __restrict__ gamma,
            const float* __restrict__ beta,
            float*       __restrict__ out) {
    __shared__ float2 s_tab[TABSZ];                       // 8 KB
    __shared__ float  sm_p[NWARPS][32][ROWS];             // 8 KB
    __shared__ float  sm_l[ROWS][NWARPS];
    __shared__ float  sm_a[ROWS][NWARPS][OUT_DIM];        // 8 KB
    __shared__ unsigned s_flag;

    const int i0    = blockIdx.x * ROWS;
    const int split = blockIdx.y;
    const int jbase = split * JCHUNK;
    const int warp  = threadIdx.x >> 5;
    const int lane  = threadIdx.x & 31;

    for (int q = threadIdx.x; q < TABSZ; q += 256)
        s_tab[q] = make_float2(g_val[q], g_val[q + 1]);
    __syncthreads();

    const float MB = g_maxdst + g_maxg;
    float src[ROWS], m[ROWS], l[ROWS], acc[ROWS];
#pragma unroll
    for (int r = 0; r < ROWS; ++r) {
        src[r] = g_src[i0 + r];
        float U = src[r] + MB;
        m[r] = fmaxf(U, 0.05f * U);   // leaky of the raw upper bound
        l[r] = 0.f;  acc[r] = 0.f;
    }

    for (int bb = warp; bb < NBATCH; bb += NWARPS) {
        const int j = jbase + bb * 32 + lane;
        const float dstj = g_dst[j];
        float p[ROWS];
#pragma unroll
        for (int r = 0; r < ROWS; ++r) {
            const int   row = i0 + r;
            const int   av  = adj[row * N + j];
            const float t_  = ts [row * N + j];
            float qf = t_ * (float)TABSZ;          // ts in [0,1)
            int   qi = __float2int_rz(qf);
            float fr = qf - (float)qi;
            float2 tt = s_tab[qi];
            float g  = fmaf(fr, tt.y - tt.x, tt.x);
            float e  = src[r] + dstj + g;
            e = fmaxf(e, 0.05f * e);               // leaky relu
            e = (av > 0) ? (e - m[r]) : -1e30f;    // mask -> p = 0
            p[r] = __expf(e);
            l[r] += p[r];
        }
        // Stage p tile to smem: 2x STS.128 per lane
        float4* pd = (float4*)&sm_p[warp][lane][0];
        pd[0] = make_float4(p[0], p[1], p[2], p[3]);
        pd[1] = make_float4(p[4], p[5], p[6], p[7]);
        __syncwarp();

        const float* zb = g_z + (jbase + bb * 32) * OUT_DIM;
#pragma unroll
        for (int jj = 0; jj < 32; ++jj) {
            float zv = zb[jj * OUT_DIM + lane];    // coalesced 128B, L2-hit
            const float4* ps = (const float4*)&sm_p[warp][jj][0];
            float4 p03 = ps[0];                    // broadcast LDS.128
            float4 p47 = ps[1];
            acc[0] = fmaf(p03.x, zv, acc[0]);
            acc[1] = fmaf(p03.y, zv, acc[1]);
            acc[2] = fmaf(p03.z, zv, acc[2]);
            acc[3] = fmaf(p03.w, zv, acc[3]);
            acc[4] = fmaf(p47.x, zv, acc[4]);
            acc[5] = fmaf(p47.y, zv, acc[5]);
            acc[6] = fmaf(p47.z, zv, acc[6]);
            acc[7] = fmaf(p47.w, zv, acc[7]);
        }
        __syncwarp();
    }

    // Reduce l within warp; stash partials for cross-warp combine.
#pragma unroll
    for (int r = 0; r < ROWS; ++r) {
        float lv = l[r];
#pragma unroll
        for (int o = 16; o > 0; o >>= 1)
            lv += __shfl_xor_sync(0xffffffffu, lv, o);
        if (lane == 0) sm_l[r][warp] = lv;
        sm_a[r][warp][lane] = acc[r];
    }
    __syncthreads();

    // Warp r writes partial for row i0+r, this split.
    {
        const int r = warp;
        const int i = i0 + r;
        float L = 0.f, A = 0.f;
#pragma unroll
        for (int w = 0; w < NWARPS; ++w) {
            L += sm_l[r][w];
            A += sm_a[r][w][lane];
        }
        g_pa[(i * JSPLIT + split) * OUT_DIM + lane] = A;
        if (lane == 0) g_pl[i * JSPLIT + split] = L;
    }

    // Elect the last split-block of this row-group as finisher.
    __threadfence();
    if (threadIdx.x == 0)
        s_flag = (atomicAdd(&g_cnt[blockIdx.x], 1) == JSPLIT - 1) ? 1u : 0u;
    __syncthreads();

    if (s_flag) {
        __threadfence();                 // see other splits' partials
        const int r = warp;              // warp r -> row i0+r
        const int i = i0 + r;
        float A = 0.f, L = 0.f;
#pragma unroll
        for (int s = 0; s < JSPLIT; ++s) {
            A += g_pa[(i * JSPLIT + s) * OUT_DIM + lane];
            L += g_pl[i * JSPLIT + s];
        }
        float temp = A / L + g_z[i * OUT_DIM + lane];

        float mu = temp;
#pragma unroll
        for (int o = 16; o > 0; o >>= 1)
            mu += __shfl_xor_sync(0xffffffffu, mu, o);
        mu *= (1.0f / OUT_DIM);
        float d = temp - mu;
        float v = d * d;
#pragma unroll
        for (int o = 16; o > 0; o >>= 1)
            v += __shfl_xor_sync(0xffffffffu, v, o);
        v *= (1.0f / OUT_DIM);
        out[i * OUT_DIM + lane] =
            d * rsqrtf(v + 1e-6f) * gamma[lane] + beta[lane];

        if (threadIdx.x == 0) {
            g_cnt[blockIdx.x] = 0;       // re-arm for next replay
            if (atomicAdd(&g_done, 1) == NGROUPS - 1) {
                g_maxdst = -1e30f;       // all blocks have read MB by now
                g_maxg   = -1e30f;
                g_done   = 0;
            }
        }
    }
}

// ---------------------------------------------------------------------------
extern "C" void kernel_launch(void* const* d_in, const int* in_sizes, int n_in,
                              void* d_out, int out_size) {
    const float* feat = (const float*)d_in[0];   // (2048,128) f32
    const int*   adj  = (const int*)  d_in[1];   // (2048,2048) i32
    const float* ts   = (const float*)d_in[2];   // (2048,2048) f32
    const float* a    = (const float*)d_in[3];   // (64,1) f32
    const int*   te   = (const int*)  d_in[4];   // scalar int
    const float* W    = (const float*)d_in[5];   // (128,32) f32
    const float* bf   = (const float*)d_in[6];   // (32,) f32
    const float* gam  = (const float*)d_in[7];   // (32,) f32
    const float* bet  = (const float*)d_in[8];   // (32,) f32
    float* out = (float*)d_out;                  // (2048,32) f32

    prep_kernel<<<PREP_BLKS + TAB_BLKS, 256>>>(feat, a, W, te, bf);
    dim3 grid(NGROUPS, JSPLIT);
    attn_kernel<<<grid, 256>>>(adj, ts, gam, bet, out);
}